// round 1
// baseline (speedup 1.0000x reference)
#include <cuda_runtime.h>
#include <math.h>

// Problem constants
#define BSZ 8
#define TSEQ 1024
#define DM 512
#define HN 8
#define HDIM 64
#define LNUM 4
#define FFD 2048
#define NCLS 10
#define NTOK (BSZ * TSEQ)   // 8192

// ---------------- scratch (device globals; no allocations allowed) ----------
__device__ float g_x  [NTOK * DM];
__device__ float g_h  [NTOK * DM];
__device__ float g_q  [NTOK * DM];
__device__ float g_k  [NTOK * DM];
__device__ float g_v  [NTOK * DM];
__device__ float g_att[NTOK * DM];
__device__ float g_ff [NTOK * FFD];
__device__ float g_pool[BSZ * DM];

// ---------------- embedding + positional encoding ---------------------------
__global__ void embed_kernel(const int* __restrict__ tokens,
                             const float* __restrict__ emb,
                             float* __restrict__ x) {
    int row = blockIdx.x;            // 0..8191  = b*T + t
    int t   = row & (TSEQ - 1);
    int tok = tokens[row];
    int d0  = threadIdx.x * 4;       // 128 threads * 4 = 512
    float4 e = *(const float4*)&emb[(size_t)tok * DM + d0];
    float vals[4] = {e.x, e.y, e.z, e.w};
    const float neg_ln1e4_over_D = -9.210340371976184f / (float)DM;
#pragma unroll
    for (int i = 0; i < 4; i++) {
        int d = d0 + i;
        int pair = d >> 1;
        float freq = expf((float)(2 * pair) * neg_ln1e4_over_D);
        float ang  = (float)t * freq;
        vals[i] += (d & 1) ? cosf(ang) : sinf(ang);
    }
    float4 o = {vals[0], vals[1], vals[2], vals[3]};
    *(float4*)&x[(size_t)row * DM + d0] = o;
}

// ---------------- layernorm (one block per row, 128 threads * 4 elems) ------
__global__ void ln_kernel(const float* __restrict__ in, float* __restrict__ out,
                          const float* __restrict__ gw, const float* __restrict__ bw) {
    int row = blockIdx.x;
    int tid = threadIdx.x;
    float4 v = *(const float4*)&in[(size_t)row * DM + tid * 4];
    float s  = v.x + v.y + v.z + v.w;
    float ss = v.x*v.x + v.y*v.y + v.z*v.z + v.w*v.w;
#pragma unroll
    for (int o = 16; o > 0; o >>= 1) {
        s  += __shfl_xor_sync(0xffffffffu, s,  o);
        ss += __shfl_xor_sync(0xffffffffu, ss, o);
    }
    __shared__ float sm[4], sm2[4];
    int w = tid >> 5;
    if ((tid & 31) == 0) { sm[w] = s; sm2[w] = ss; }
    __syncthreads();
    float S  = sm[0] + sm[1] + sm[2] + sm[3];
    float SS = sm2[0] + sm2[1] + sm2[2] + sm2[3];
    float mean = S * (1.0f / DM);
    float var  = SS * (1.0f / DM) - mean * mean;
    float rstd = rsqrtf(var + 1e-5f);
    float4 gv = *(const float4*)&gw[tid * 4];
    float4 bv = *(const float4*)&bw[tid * 4];
    float4 o;
    o.x = (v.x - mean) * rstd * gv.x + bv.x;
    o.y = (v.y - mean) * rstd * gv.y + bv.y;
    o.z = (v.z - mean) * rstd * gv.z + bv.z;
    o.w = (v.w - mean) * rstd * gv.w + bv.w;
    *(float4*)&out[(size_t)row * DM + tid * 4] = o;
}

// ---------------- SGEMM: C = op(A @ B + bias [+ res]) -----------------------
// 128x128 tile, K-tile 16, 256 threads, 8x8 per thread.
// OP: 0 = none, 1 = add residual, 2 = exact GELU, 3 = tanh
template <int OP>
__global__ void __launch_bounds__(256)
sgemm_kernel(const float* __restrict__ A, const float* __restrict__ B,
             const float* __restrict__ bias, const float* __restrict__ res,
             float* __restrict__ C, int M, int N, int K) {
    __shared__ float As[16][128];
    __shared__ float Bs[16][128];
    int tid = threadIdx.x;
    int tx = tid & 15;        // 0..15 -> cols
    int ty = tid >> 4;        // 0..15 -> rows
    int row0 = blockIdx.y * 128;
    int col0 = blockIdx.x * 128;
    const float* Aptr = A + (size_t)row0 * K;
    const float* Bptr = B + col0;
    float acc[8][8];
#pragma unroll
    for (int i = 0; i < 8; i++)
#pragma unroll
        for (int j = 0; j < 8; j++) acc[i][j] = 0.f;

    for (int k0 = 0; k0 < K; k0 += 16) {
#pragma unroll
        for (int u = 0; u < 2; u++) {
            int idx = tid + u * 256;
            // A: 128 rows x 16 k  (load float4 along k, store transposed)
            int r  = idx >> 2, kq = idx & 3;
            float4 av = *(const float4*)&Aptr[(size_t)r * K + k0 + kq * 4];
            As[kq * 4 + 0][r] = av.x;
            As[kq * 4 + 1][r] = av.y;
            As[kq * 4 + 2][r] = av.z;
            As[kq * 4 + 3][r] = av.w;
            // B: 16 k x 128 n (direct float4 copy)
            int kB = idx >> 5, nq = idx & 31;
            float4 bv = *(const float4*)&Bptr[(size_t)(k0 + kB) * N + nq * 4];
            *(float4*)&Bs[kB][nq * 4] = bv;
        }
        __syncthreads();
#pragma unroll
        for (int kk = 0; kk < 16; kk++) {
            float a[8], b[8];
            *(float4*)&a[0] = *(const float4*)&As[kk][ty * 8];
            *(float4*)&a[4] = *(const float4*)&As[kk][ty * 8 + 4];
            *(float4*)&b[0] = *(const float4*)&Bs[kk][tx * 8];
            *(float4*)&b[4] = *(const float4*)&Bs[kk][tx * 8 + 4];
#pragma unroll
            for (int i = 0; i < 8; i++)
#pragma unroll
                for (int j = 0; j < 8; j++)
                    acc[i][j] = fmaf(a[i], b[j], acc[i][j]);
        }
        __syncthreads();
    }
    // epilogue
    float bvals[8];
#pragma unroll
    for (int j = 0; j < 8; j++)
        bvals[j] = bias ? bias[col0 + tx * 8 + j] : 0.f;
#pragma unroll
    for (int i = 0; i < 8; i++) {
        int r = row0 + ty * 8 + i;
        float* cp = &C[(size_t)r * N + col0 + tx * 8];
        const float* rp = (OP == 1) ? &res[(size_t)r * N + col0 + tx * 8] : nullptr;
        float o[8];
#pragma unroll
        for (int j = 0; j < 8; j++) {
            float v = acc[i][j] + bvals[j];
            if (OP == 1) v += rp[j];
            if (OP == 2) v = 0.5f * v * (1.0f + erff(v * 0.70710678118654752f));
            if (OP == 3) v = tanhf(v);
            o[j] = v;
        }
        *(float4*)&cp[0] = *(float4*)&o[0];
        *(float4*)&cp[4] = *(float4*)&o[4];
    }
}

// ---------------- attention: one thread per query, online softmax ----------
// grid (B*H, T/128), block 128.  Q/K/V layout: [B*T, D] with head slice
// [h*64, h*64+64) contiguous.
__global__ void __launch_bounds__(128)
attn_kernel(const float* __restrict__ Q, const float* __restrict__ Kp,
            const float* __restrict__ V, float* __restrict__ O) {
    int bh = blockIdx.x;          // 0..63
    int b  = bh >> 3, h = bh & 7;
    int qrow = blockIdx.y * 128 + threadIdx.x;   // within T
    const float* qp = Q + ((size_t)(b * TSEQ + qrow) * DM) + h * HDIM;
    float qreg[HDIM];
#pragma unroll
    for (int i = 0; i < 16; i++) {
        float4 v4 = *(const float4*)&qp[i * 4];
        qreg[i * 4 + 0] = v4.x; qreg[i * 4 + 1] = v4.y;
        qreg[i * 4 + 2] = v4.z; qreg[i * 4 + 3] = v4.w;
    }
    float m = -1e30f, l = 0.f;
    float acc[HDIM];
#pragma unroll
    for (int d = 0; d < HDIM; d++) acc[d] = 0.f;

    __shared__ float Ks[64][64];
    __shared__ float Vs[64][64];
    const float scale = 0.125f;   // 1/sqrt(64)

    for (int kt = 0; kt < TSEQ; kt += 64) {
        __syncthreads();
#pragma unroll
        for (int u = 0; u < 8; u++) {
            int idx = threadIdx.x + u * 128;
            int r = idx >> 4, c = (idx & 15) * 4;
            size_t base = ((size_t)(b * TSEQ + kt + r) * DM) + h * HDIM + c;
            *(float4*)&Ks[r][c] = *(const float4*)&Kp[base];
            *(float4*)&Vs[r][c] = *(const float4*)&V[base];
        }
        __syncthreads();
        for (int j = 0; j < 64; j++) {
            float s = 0.f;
#pragma unroll
            for (int d = 0; d < 64; d += 4) {
                float4 kv = *(const float4*)&Ks[j][d];
                s = fmaf(qreg[d + 0], kv.x, s);
                s = fmaf(qreg[d + 1], kv.y, s);
                s = fmaf(qreg[d + 2], kv.z, s);
                s = fmaf(qreg[d + 3], kv.w, s);
            }
            s *= scale;
            if (s <= m) {
                float p = expf(s - m);
                l += p;
#pragma unroll
                for (int d = 0; d < 64; d += 4) {
                    float4 vv = *(const float4*)&Vs[j][d];
                    acc[d + 0] = fmaf(p, vv.x, acc[d + 0]);
                    acc[d + 1] = fmaf(p, vv.y, acc[d + 1]);
                    acc[d + 2] = fmaf(p, vv.z, acc[d + 2]);
                    acc[d + 3] = fmaf(p, vv.w, acc[d + 3]);
                }
            } else {
                float corr = expf(m - s);
                m = s;
                l = l * corr + 1.0f;
#pragma unroll
                for (int d = 0; d < 64; d += 4) {
                    float4 vv = *(const float4*)&Vs[j][d];
                    acc[d + 0] = fmaf(acc[d + 0], corr, vv.x);
                    acc[d + 1] = fmaf(acc[d + 1], corr, vv.y);
                    acc[d + 2] = fmaf(acc[d + 2], corr, vv.z);
                    acc[d + 3] = fmaf(acc[d + 3], corr, vv.w);
                }
            }
        }
    }
    float inv = 1.0f / l;
    float* op = O + ((size_t)(b * TSEQ + qrow) * DM) + h * HDIM;
#pragma unroll
    for (int i = 0; i < 16; i++) {
        float4 o4;
        o4.x = acc[i * 4 + 0] * inv;
        o4.y = acc[i * 4 + 1] * inv;
        o4.z = acc[i * 4 + 2] * inv;
        o4.w = acc[i * 4 + 3] * inv;
        *(float4*)&op[i * 4] = o4;
    }
}

// ---------------- mean pool over T ------------------------------------------
__global__ void pool_kernel(const float* __restrict__ X, float* __restrict__ P) {
    int b = blockIdx.x;
    int d = blockIdx.y * 128 + threadIdx.x;
    float s = 0.f;
    for (int t = 0; t < TSEQ; t++)
        s += X[((size_t)(b * TSEQ + t)) * DM + d];
    P[b * DM + d] = s * (1.0f / TSEQ);
}

// ---------------- classifier ------------------------------------------------
__global__ void cls_kernel(const float* __restrict__ P, const float* __restrict__ W,
                           const float* __restrict__ bias, float* __restrict__ out) {
    int b = blockIdx.x / NCLS;
    int c = blockIdx.x % NCLS;
    int tid = threadIdx.x;   // 128
    float s = 0.f;
    for (int d = tid; d < DM; d += 128)
        s += P[b * DM + d] * W[(size_t)d * NCLS + c];
#pragma unroll
    for (int o = 16; o > 0; o >>= 1) s += __shfl_xor_sync(0xffffffffu, s, o);
    __shared__ float sm[4];
    if ((tid & 31) == 0) sm[tid >> 5] = s;
    __syncthreads();
    if (tid == 0) out[b * NCLS + c] = sm[0] + sm[1] + sm[2] + sm[3] + bias[c];
}

// ---------------- launch ----------------------------------------------------
extern "C" void kernel_launch(void* const* d_in, const int* in_sizes, int n_in,
                              void* d_out, int out_size) {
    const int*   tokens = (const int*)  d_in[0];
    const float* emb    = (const float*)d_in[1];
    const float* Wq     = (const float*)d_in[2];
    const float* bq     = (const float*)d_in[3];
    const float* Wk     = (const float*)d_in[4];
    const float* bk     = (const float*)d_in[5];
    const float* Wv     = (const float*)d_in[6];
    const float* bv     = (const float*)d_in[7];
    const float* Wo     = (const float*)d_in[8];
    const float* bo     = (const float*)d_in[9];
    const float* ln1_g  = (const float*)d_in[10];
    const float* ln1_b  = (const float*)d_in[11];
    const float* ln2_g  = (const float*)d_in[12];
    const float* ln2_b  = (const float*)d_in[13];
    const float* W1     = (const float*)d_in[14];
    const float* b1     = (const float*)d_in[15];
    const float* W2     = (const float*)d_in[16];
    const float* b2     = (const float*)d_in[17];
    const float* heavy_w  = (const float*)d_in[18];
    const float* heavy_b  = (const float*)d_in[19];
    const float* heavy_a1 = (const float*)d_in[20];
    const float* heavy_a2 = (const float*)d_in[21];
    const float* norm_g = (const float*)d_in[22];
    const float* norm_b = (const float*)d_in[23];
    const float* cls_W  = (const float*)d_in[24];
    const float* cls_b  = (const float*)d_in[25];
    float* out = (float*)d_out;

    float *x, *h, *q, *k, *v, *att, *ff, *pool;
    cudaGetSymbolAddress((void**)&x,    g_x);
    cudaGetSymbolAddress((void**)&h,    g_h);
    cudaGetSymbolAddress((void**)&q,    g_q);
    cudaGetSymbolAddress((void**)&k,    g_k);
    cudaGetSymbolAddress((void**)&v,    g_v);
    cudaGetSymbolAddress((void**)&att,  g_att);
    cudaGetSymbolAddress((void**)&ff,   g_ff);
    cudaGetSymbolAddress((void**)&pool, g_pool);

    embed_kernel<<<NTOK, 128>>>(tokens, emb, x);

    dim3 gD(DM / 128, NTOK / 128);    // (4, 64)
    dim3 gF(FFD / 128, NTOK / 128);   // (16, 64)

    for (int l = 0; l < LNUM; l++) {
        const float* wq = Wq + (size_t)l * DM * DM;
        const float* wk = Wk + (size_t)l * DM * DM;
        const float* wv = Wv + (size_t)l * DM * DM;
        const float* wo = Wo + (size_t)l * DM * DM;

        ln_kernel<<<NTOK, 128>>>(x, h, ln1_g + l * DM, ln1_b + l * DM);
        sgemm_kernel<0><<<gD, 256>>>(h, wq, bq + l * DM, nullptr, q, NTOK, DM, DM);
        sgemm_kernel<0><<<gD, 256>>>(h, wk, bk + l * DM, nullptr, k, NTOK, DM, DM);
        sgemm_kernel<0><<<gD, 256>>>(h, wv, bv + l * DM, nullptr, v, NTOK, DM, DM);
        attn_kernel<<<dim3(BSZ * HN, TSEQ / 128), 128>>>(q, k, v, att);
        sgemm_kernel<1><<<gD, 256>>>(att, wo, bo + l * DM, x, x, NTOK, DM, DM);

        ln_kernel<<<NTOK, 128>>>(x, h, ln2_g + l * DM, ln2_b + l * DM);
        sgemm_kernel<2><<<gF, 256>>>(h, W1 + (size_t)l * DM * FFD, b1 + l * FFD,
                                     nullptr, ff, NTOK, FFD, DM);
        sgemm_kernel<1><<<gD, 256>>>(ff, W2 + (size_t)l * FFD * DM, b2 + l * DM,
                                     x, x, NTOK, DM, FFD);
    }

    // heavy: tanh(((x @ heavy_w) @ heavy_a1) @ heavy_a2 + heavy_b)
    sgemm_kernel<0><<<gD, 256>>>(x, heavy_w,  nullptr, nullptr, h, NTOK, DM, DM);
    sgemm_kernel<0><<<gD, 256>>>(h, heavy_a1, nullptr, nullptr, q, NTOK, DM, DM);
    sgemm_kernel<3><<<gD, 256>>>(q, heavy_a2, heavy_b, nullptr, h, NTOK, DM, DM);

    ln_kernel<<<NTOK, 128>>>(h, x, norm_g, norm_b);
    pool_kernel<<<dim3(BSZ, DM / 128), 128>>>(x, pool);
    cls_kernel<<<BSZ * NCLS, 128>>>(pool, cls_W, cls_b, out);
    (void)in_sizes; (void)n_in; (void)out_size;
}

// round 3
// speedup vs baseline: 1.5709x; 1.5709x over previous
#include <cuda_runtime.h>
#include <cuda_bf16.h>
#include <math.h>
#include <stdint.h>

// Problem constants
#define BSZ 8
#define TSEQ 1024
#define DM 512
#define HN 8
#define HDIM 64
#define LNUM 4
#define FFD 2048
#define NCLS 10
#define NTOK (BSZ * TSEQ)   // 8192

// ---------------- scratch (device globals; no allocations allowed) ----------
__device__ float g_x  [NTOK * DM];
__device__ float g_h  [NTOK * DM];
__device__ float g_q  [NTOK * DM];
__device__ float g_k  [NTOK * DM];
__device__ float g_v  [NTOK * DM];
__device__ float g_att[NTOK * DM];
__device__ float g_ff [NTOK * FFD];
__device__ float g_pool[BSZ * DM];

// transposed + split weights: per layer [Wq,Wk,Wv,Wo each 512x512][W1 2048x512][W2 512x2048]
#define LSTRIDE (4 * DM * DM + DM * FFD + FFD * DM)   // 3,145,728
#define WT_TOT  (LNUM * LSTRIDE + 3 * DM * DM)
__device__ __nv_bfloat16 g_wt_hi[WT_TOT];
__device__ __nv_bfloat16 g_wt_lo[WT_TOT];

// ---------------- helpers ----------------------------------------------------
__device__ __forceinline__ uint32_t smem_u32(const void* p) {
    uint32_t a;
    asm("{ .reg .u64 t; cvta.to.shared.u64 t, %1; cvt.u32.u64 %0, t; }" : "=r"(a) : "l"(p));
    return a;
}
__device__ __forceinline__ void ldm_x4(uint32_t* r, uint32_t addr) {
    asm volatile("ldmatrix.sync.aligned.m8n8.x4.shared.b16 {%0,%1,%2,%3}, [%4];"
                 : "=r"(r[0]), "=r"(r[1]), "=r"(r[2]), "=r"(r[3]) : "r"(addr));
}
__device__ __forceinline__ void mma_bf16(float* d, const uint32_t* a, const uint32_t* b) {
    asm volatile("mma.sync.aligned.m16n8k16.row.col.f32.bf16.bf16.f32 "
                 "{%0,%1,%2,%3}, {%4,%5,%6,%7}, {%8,%9}, {%0,%1,%2,%3};"
                 : "+f"(d[0]), "+f"(d[1]), "+f"(d[2]), "+f"(d[3])
                 : "r"(a[0]), "r"(a[1]), "r"(a[2]), "r"(a[3]), "r"(b[0]), "r"(b[1]));
}
__device__ __forceinline__ uint32_t packbf(__nv_bfloat16 a, __nv_bfloat16 b) {
    __nv_bfloat162 t = __halves2bfloat162(a, b);
    return *reinterpret_cast<uint32_t*>(&t);
}
__device__ __forceinline__ void split2(float a, float b, uint32_t& hi, uint32_t& lo) {
    __nv_bfloat16 ha = __float2bfloat16(a), hb = __float2bfloat16(b);
    __nv_bfloat16 la = __float2bfloat16(a - __bfloat162float(ha));
    __nv_bfloat16 lb = __float2bfloat16(b - __bfloat162float(hb));
    hi = packbf(ha, hb);
    lo = packbf(la, lb);
}

// ---------------- weight transpose + bf16 split ------------------------------
// W [K,N] fp32 -> Wh/Wl [N,K] bf16
__global__ void tsplit_kernel(const float* __restrict__ W, __nv_bfloat16* __restrict__ Wh,
                              __nv_bfloat16* __restrict__ Wl, int K, int N) {
    __shared__ float tile[32][33];
    int n0 = blockIdx.x * 32, k0 = blockIdx.y * 32;
    int tx = threadIdx.x, ty = threadIdx.y;   // (32, 8)
#pragma unroll
    for (int i = 0; i < 4; i++)
        tile[ty + i * 8][tx] = W[(size_t)(k0 + ty + i * 8) * N + n0 + tx];
    __syncthreads();
#pragma unroll
    for (int i = 0; i < 4; i++) {
        int n = ty + i * 8;
        float v = tile[tx][n];
        __nv_bfloat16 h = __float2bfloat16(v);
        __nv_bfloat16 l = __float2bfloat16(v - __bfloat162float(h));
        size_t o = (size_t)(n0 + n) * K + k0 + tx;
        Wh[o] = h;
        Wl[o] = l;
    }
}

// ---------------- HMMA GEMM: C[M,N] = op(A[M,K] @ Wt^T + bias [+res]) -------
// Wt stored [N,K] bf16 (hi/lo).  Block tile 128x128, K-chunk 32, 256 threads.
// 3-pass split-bf16: AhBh + AhBl + AlBh.
// OP: 0 none, 1 +res, 2 exact GELU, 3 tanh
#define KC 32
#define SPAD 40   // padded row length (bf16 elems); 80B stride -> ldmatrix conflict-free

template <int OP>
__global__ void __launch_bounds__(256, 2)
gemm_mma(const float* __restrict__ A, const __nv_bfloat16* __restrict__ Wh,
         const __nv_bfloat16* __restrict__ Wl, const float* __restrict__ bias,
         const float* __restrict__ res, float* __restrict__ C, int K, int N) {
    __shared__ __nv_bfloat16 Ah[128][SPAD];
    __shared__ __nv_bfloat16 Al[128][SPAD];
    __shared__ __nv_bfloat16 Bh[128][SPAD];
    __shared__ __nv_bfloat16 Bl[128][SPAD];

    int tid = threadIdx.x;
    int wid = tid >> 5, l = tid & 31;
    int wm = wid & 3, wn = wid >> 2;          // 4m x 2n warps, warp tile 32x64
    int m0 = blockIdx.y * 128, n0 = blockIdx.x * 128;

    // per-lane ldmatrix source addresses (byte offsets into padded smem rows)
    uint32_t AhB = smem_u32(&Ah[0][0]), AlB = smem_u32(&Al[0][0]);
    uint32_t BhB = smem_u32(&Bh[0][0]), BlB = smem_u32(&Bl[0][0]);
    // A frag: lanes 0-15 rows 0-15 (k-lo), 16-31 same rows (k-hi)
    int ar = (l & 15), acb = l >> 4;
    uint32_t aoff = (uint32_t)((wm * 32 + ar) * (SPAD * 2) + acb * 16);
    // B frag: lanes 0-15 atom q (cb = k-block), 16-31 atom q+1
    int br = (l & 7) + ((l >> 4) << 3);
    int bcb = (l >> 3) & 1;
    uint32_t boff = (uint32_t)((wn * 64 + br) * (SPAD * 2) + bcb * 16);

    float acc[2][8][4];
#pragma unroll
    for (int i = 0; i < 2; i++)
#pragma unroll
        for (int j = 0; j < 8; j++)
#pragma unroll
            for (int u = 0; u < 4; u++) acc[i][j][u] = 0.f;

    const int nchunks = K / KC;
    for (int ck = 0; ck < nchunks; ck++) {
        int k0 = ck * KC;
        // ---- load A tile 128x32 fp32 -> split hi/lo ----
        const float* Ab = A + (size_t)m0 * K + k0;
#pragma unroll
        for (int i = 0; i < 4; i++) {
            int idx = tid + i * 256;
            int r = idx >> 3, q = idx & 7;
            float4 a4 = *(const float4*)(Ab + (size_t)r * K + q * 4);
            uint32_t h0, l0, h1, l1;
            split2(a4.x, a4.y, h0, l0);
            split2(a4.z, a4.w, h1, l1);
            *(uint2*)(&Ah[r][q * 4]) = make_uint2(h0, h1);
            *(uint2*)(&Al[r][q * 4]) = make_uint2(l0, l1);
        }
        // ---- load B tiles 128x32 bf16 (hi/lo) ----
        const __nv_bfloat16* WhB = Wh + (size_t)n0 * K + k0;
        const __nv_bfloat16* WlB = Wl + (size_t)n0 * K + k0;
#pragma unroll
        for (int i = 0; i < 2; i++) {
            int idx = tid + i * 256;
            int r = idx >> 2, q = idx & 3;
            *(uint4*)(&Bh[r][q * 8]) = *(const uint4*)(WhB + (size_t)r * K + q * 8);
            *(uint4*)(&Bl[r][q * 8]) = *(const uint4*)(WlB + (size_t)r * K + q * 8);
        }
        __syncthreads();

        // ---- compute: 2 k-steps of 16 ----
#pragma unroll
        for (int ks = 0; ks < KC; ks += 16) {
            uint32_t ah[2][4], al[2][4];
#pragma unroll
            for (int ma = 0; ma < 2; ma++) {
                ldm_x4(ah[ma], AhB + aoff + (uint32_t)(ma * 16 * SPAD * 2 + ks * 2));
                ldm_x4(al[ma], AlB + aoff + (uint32_t)(ma * 16 * SPAD * 2 + ks * 2));
            }
#pragma unroll
            for (int nh = 0; nh < 2; nh++) {
                uint32_t bh[4][2], bl[4][2];
#pragma unroll
                for (int nq = 0; nq < 2; nq++) {
                    uint32_t r4[4];
                    uint32_t o = boff + (uint32_t)((nh * 32 + nq * 16) * SPAD * 2 + ks * 2);
                    ldm_x4(r4, BhB + o);
                    bh[nq * 2][0] = r4[0]; bh[nq * 2][1] = r4[1];
                    bh[nq * 2 + 1][0] = r4[2]; bh[nq * 2 + 1][1] = r4[3];
                    ldm_x4(r4, BlB + o);
                    bl[nq * 2][0] = r4[0]; bl[nq * 2][1] = r4[1];
                    bl[nq * 2 + 1][0] = r4[2]; bl[nq * 2 + 1][1] = r4[3];
                }
#pragma unroll
                for (int ma = 0; ma < 2; ma++)
#pragma unroll
                    for (int na = 0; na < 4; na++) {
                        float* d = acc[ma][nh * 4 + na];
                        mma_bf16(d, ah[ma], bh[na]);
                        mma_bf16(d, ah[ma], bl[na]);
                        mma_bf16(d, al[ma], bh[na]);
                    }
            }
        }
        __syncthreads();
    }

    // ---- epilogue ----
#pragma unroll
    for (int ma = 0; ma < 2; ma++) {
        int row0 = m0 + wm * 32 + ma * 16 + (l >> 2);
#pragma unroll
        for (int na = 0; na < 8; na++) {
            int col = n0 + wn * 64 + na * 8 + (l & 3) * 2;
            float b0 = bias ? bias[col] : 0.f;
            float b1 = bias ? bias[col + 1] : 0.f;
#pragma unroll
            for (int half = 0; half < 2; half++) {
                int row = row0 + half * 8;
                float v0 = acc[ma][na][half * 2 + 0] + b0;
                float v1 = acc[ma][na][half * 2 + 1] + b1;
                if (OP == 1) {
                    const float* rp = res + (size_t)row * N + col;
                    v0 += rp[0]; v1 += rp[1];
                }
                if (OP == 2) {
                    v0 = 0.5f * v0 * (1.0f + erff(v0 * 0.70710678118654752f));
                    v1 = 0.5f * v1 * (1.0f + erff(v1 * 0.70710678118654752f));
                }
                if (OP == 3) { v0 = tanhf(v0); v1 = tanhf(v1); }
                float2 o2 = make_float2(v0, v1);
                *(float2*)(C + (size_t)row * N + col) = o2;
            }
        }
    }
}

// ---------------- embedding + positional encoding ---------------------------
__global__ void embed_kernel(const int* __restrict__ tokens,
                             const float* __restrict__ emb,
                             float* __restrict__ x) {
    int row = blockIdx.x;
    int t   = row & (TSEQ - 1);
    int tok = tokens[row];
    int d0  = threadIdx.x * 4;
    float4 e = *(const float4*)&emb[(size_t)tok * DM + d0];
    float vals[4] = {e.x, e.y, e.z, e.w};
    const float c = -9.210340371976184f / (float)DM;
#pragma unroll
    for (int i = 0; i < 4; i++) {
        int d = d0 + i;
        float freq = expf((float)(2 * (d >> 1)) * c);
        float ang  = (float)t * freq;
        vals[i] += (d & 1) ? cosf(ang) : sinf(ang);
    }
    float4 o = {vals[0], vals[1], vals[2], vals[3]};
    *(float4*)&x[(size_t)row * DM + d0] = o;
}

// ---------------- layernorm --------------------------------------------------
__global__ void ln_kernel(const float* __restrict__ in, float* __restrict__ out,
                          const float* __restrict__ gw, const float* __restrict__ bw) {
    int row = blockIdx.x;
    int tid = threadIdx.x;
    float4 v = *(const float4*)&in[(size_t)row * DM + tid * 4];
    float s  = v.x + v.y + v.z + v.w;
    float ss = v.x*v.x + v.y*v.y + v.z*v.z + v.w*v.w;
#pragma unroll
    for (int o = 16; o > 0; o >>= 1) {
        s  += __shfl_xor_sync(0xffffffffu, s,  o);
        ss += __shfl_xor_sync(0xffffffffu, ss, o);
    }
    __shared__ float sm[4], sm2[4];
    int w = tid >> 5;
    if ((tid & 31) == 0) { sm[w] = s; sm2[w] = ss; }
    __syncthreads();
    float S  = sm[0] + sm[1] + sm[2] + sm[3];
    float SS = sm2[0] + sm2[1] + sm2[2] + sm2[3];
    float mean = S * (1.0f / DM);
    float var  = SS * (1.0f / DM) - mean * mean;
    float rstd = rsqrtf(var + 1e-5f);
    float4 gv = *(const float4*)&gw[tid * 4];
    float4 bv = *(const float4*)&bw[tid * 4];
    float4 o;
    o.x = (v.x - mean) * rstd * gv.x + bv.x;
    o.y = (v.y - mean) * rstd * gv.y + bv.y;
    o.z = (v.z - mean) * rstd * gv.z + bv.z;
    o.w = (v.w - mean) * rstd * gv.w + bv.w;
    *(float4*)&out[(size_t)row * DM + tid * 4] = o;
}

// ---------------- attention (fp32, online softmax) ---------------------------
__global__ void __launch_bounds__(128)
attn_kernel(const float* __restrict__ Q, const float* __restrict__ Kp,
            const float* __restrict__ V, float* __restrict__ O) {
    int bh = blockIdx.x;
    int b  = bh >> 3, h = bh & 7;
    int qrow = blockIdx.y * 128 + threadIdx.x;
    const float* qp = Q + ((size_t)(b * TSEQ + qrow) * DM) + h * HDIM;
    float qreg[HDIM];
#pragma unroll
    for (int i = 0; i < 16; i++) {
        float4 v4 = *(const float4*)&qp[i * 4];
        qreg[i*4+0] = v4.x; qreg[i*4+1] = v4.y; qreg[i*4+2] = v4.z; qreg[i*4+3] = v4.w;
    }
    float m = -1e30f, lsum = 0.f;
    float acc[HDIM];
#pragma unroll
    for (int d = 0; d < HDIM; d++) acc[d] = 0.f;

    __shared__ float Ks[64][64];
    __shared__ float Vs[64][64];
    const float scale = 0.125f;

    for (int kt = 0; kt < TSEQ; kt += 64) {
        __syncthreads();
#pragma unroll
        for (int u = 0; u < 8; u++) {
            int idx = threadIdx.x + u * 128;
            int r = idx >> 4, c = (idx & 15) * 4;
            size_t base = ((size_t)(b * TSEQ + kt + r) * DM) + h * HDIM + c;
            *(float4*)&Ks[r][c] = *(const float4*)&Kp[base];
            *(float4*)&Vs[r][c] = *(const float4*)&V[base];
        }
        __syncthreads();
        for (int j = 0; j < 64; j++) {
            float s = 0.f;
#pragma unroll
            for (int d = 0; d < 64; d += 4) {
                float4 kv = *(const float4*)&Ks[j][d];
                s = fmaf(qreg[d+0], kv.x, s);
                s = fmaf(qreg[d+1], kv.y, s);
                s = fmaf(qreg[d+2], kv.z, s);
                s = fmaf(qreg[d+3], kv.w, s);
            }
            s *= scale;
            if (s <= m) {
                float p = expf(s - m);
                lsum += p;
#pragma unroll
                for (int d = 0; d < 64; d += 4) {
                    float4 vv = *(const float4*)&Vs[j][d];
                    acc[d+0] = fmaf(p, vv.x, acc[d+0]);
                    acc[d+1] = fmaf(p, vv.y, acc[d+1]);
                    acc[d+2] = fmaf(p, vv.z, acc[d+2]);
                    acc[d+3] = fmaf(p, vv.w, acc[d+3]);
                }
            } else {
                float corr = expf(m - s);
                m = s;
                lsum = lsum * corr + 1.0f;
#pragma unroll
                for (int d = 0; d < 64; d += 4) {
                    float4 vv = *(const float4*)&Vs[j][d];
                    acc[d+0] = fmaf(acc[d+0], corr, vv.x);
                    acc[d+1] = fmaf(acc[d+1], corr, vv.y);
                    acc[d+2] = fmaf(acc[d+2], corr, vv.z);
                    acc[d+3] = fmaf(acc[d+3], corr, vv.w);
                }
            }
        }
    }
    float inv = 1.0f / lsum;
    float* op = O + ((size_t)(b * TSEQ + qrow) * DM) + h * HDIM;
#pragma unroll
    for (int i = 0; i < 16; i++) {
        float4 o4;
        o4.x = acc[i*4+0] * inv; o4.y = acc[i*4+1] * inv;
        o4.z = acc[i*4+2] * inv; o4.w = acc[i*4+3] * inv;
        *(float4*)&op[i * 4] = o4;
    }
}

// ---------------- mean pool / classifier -------------------------------------
__global__ void pool_kernel(const float* __restrict__ X, float* __restrict__ P) {
    int b = blockIdx.x;
    int d = blockIdx.y * 128 + threadIdx.x;
    float s = 0.f;
    for (int t = 0; t < TSEQ; t++)
        s += X[((size_t)(b * TSEQ + t)) * DM + d];
    P[b * DM + d] = s * (1.0f / TSEQ);
}

__global__ void cls_kernel(const float* __restrict__ P, const float* __restrict__ W,
                           const float* __restrict__ bias, float* __restrict__ out) {
    int b = blockIdx.x / NCLS;
    int c = blockIdx.x % NCLS;
    int tid = threadIdx.x;
    float s = 0.f;
    for (int d = tid; d < DM; d += 128)
        s += P[b * DM + d] * W[(size_t)d * NCLS + c];
#pragma unroll
    for (int o = 16; o > 0; o >>= 1) s += __shfl_xor_sync(0xffffffffu, s, o);
    __shared__ float sm[4];
    if ((tid & 31) == 0) sm[tid >> 5] = s;
    __syncthreads();
    if (tid == 0) out[b * NCLS + c] = sm[0] + sm[1] + sm[2] + sm[3] + bias[c];
}

// ---------------- launch ------------------------------------------------------
extern "C" void kernel_launch(void* const* d_in, const int* in_sizes, int n_in,
                              void* d_out, int out_size) {
    const int*   tokens = (const int*)  d_in[0];
    const float* emb    = (const float*)d_in[1];
    const float* Wq     = (const float*)d_in[2];
    const float* bq     = (const float*)d_in[3];
    const float* Wk     = (const float*)d_in[4];
    const float* bk     = (const float*)d_in[5];
    const float* Wv     = (const float*)d_in[6];
    const float* bv     = (const float*)d_in[7];
    const float* Wo     = (const float*)d_in[8];
    const float* bo     = (const float*)d_in[9];
    const float* ln1_g  = (const float*)d_in[10];
    const float* ln1_b  = (const float*)d_in[11];
    const float* ln2_g  = (const float*)d_in[12];
    const float* ln2_b  = (const float*)d_in[13];
    const float* W1     = (const float*)d_in[14];
    const float* b1     = (const float*)d_in[15];
    const float* W2     = (const float*)d_in[16];
    const float* b2     = (const float*)d_in[17];
    const float* heavy_w  = (const float*)d_in[18];
    const float* heavy_b  = (const float*)d_in[19];
    const float* heavy_a1 = (const float*)d_in[20];
    const float* heavy_a2 = (const float*)d_in[21];
    const float* norm_g = (const float*)d_in[22];
    const float* norm_b = (const float*)d_in[23];
    const float* cls_W  = (const float*)d_in[24];
    const float* cls_b  = (const float*)d_in[25];
    float* out = (float*)d_out;

    float *x, *h, *q, *k, *v, *att, *ff, *pool;
    __nv_bfloat16 *wth, *wtl;
    cudaGetSymbolAddress((void**)&x,    g_x);
    cudaGetSymbolAddress((void**)&h,    g_h);
    cudaGetSymbolAddress((void**)&q,    g_q);
    cudaGetSymbolAddress((void**)&k,    g_k);
    cudaGetSymbolAddress((void**)&v,    g_v);
    cudaGetSymbolAddress((void**)&att,  g_att);
    cudaGetSymbolAddress((void**)&ff,   g_ff);
    cudaGetSymbolAddress((void**)&pool, g_pool);
    cudaGetSymbolAddress((void**)&wth,  g_wt_hi);
    cudaGetSymbolAddress((void**)&wtl,  g_wt_lo);

    // -------- transpose + split all weights into [N,K] bf16 scratch ----------
    dim3 tb(32, 8);
    for (int l = 0; l < LNUM; l++) {
        size_t base = (size_t)l * LSTRIDE;
        tsplit_kernel<<<dim3(DM/32, DM/32), tb>>>(Wq + (size_t)l*DM*DM, wth + base,           wtl + base,           DM, DM);
        tsplit_kernel<<<dim3(DM/32, DM/32), tb>>>(Wk + (size_t)l*DM*DM, wth + base + DM*DM,   wtl + base + DM*DM,   DM, DM);
        tsplit_kernel<<<dim3(DM/32, DM/32), tb>>>(Wv + (size_t)l*DM*DM, wth + base + 2*DM*DM, wtl + base + 2*DM*DM, DM, DM);
        tsplit_kernel<<<dim3(DM/32, DM/32), tb>>>(Wo + (size_t)l*DM*DM, wth + base + 3*DM*DM, wtl + base + 3*DM*DM, DM, DM);
        tsplit_kernel<<<dim3(FFD/32, DM/32), tb>>>(W1 + (size_t)l*DM*FFD, wth + base + 4*DM*DM, wtl + base + 4*DM*DM, DM, FFD);
        tsplit_kernel<<<dim3(DM/32, FFD/32), tb>>>(W2 + (size_t)l*FFD*DM, wth + base + 4*DM*DM + DM*FFD, wtl + base + 4*DM*DM + DM*FFD, FFD, DM);
    }
    size_t hb = (size_t)LNUM * LSTRIDE;
    tsplit_kernel<<<dim3(DM/32, DM/32), tb>>>(heavy_w,  wth + hb,           wtl + hb,           DM, DM);
    tsplit_kernel<<<dim3(DM/32, DM/32), tb>>>(heavy_a1, wth + hb + DM*DM,   wtl + hb + DM*DM,   DM, DM);
    tsplit_kernel<<<dim3(DM/32, DM/32), tb>>>(heavy_a2, wth + hb + 2*DM*DM, wtl + hb + 2*DM*DM, DM, DM);

    embed_kernel<<<NTOK, 128>>>(tokens, emb, x);

    dim3 gD(DM / 128, NTOK / 128);    // (4, 64)
    dim3 gF(FFD / 128, NTOK / 128);   // (16, 64)

    for (int l = 0; l < LNUM; l++) {
        size_t base = (size_t)l * LSTRIDE;
        const __nv_bfloat16 *wqh = wth + base,           *wql = wtl + base;
        const __nv_bfloat16 *wkh = wth + base + DM*DM,   *wkl = wtl + base + DM*DM;
        const __nv_bfloat16 *wvh = wth + base + 2*DM*DM, *wvl = wtl + base + 2*DM*DM;
        const __nv_bfloat16 *woh = wth + base + 3*DM*DM, *wol = wtl + base + 3*DM*DM;
        const __nv_bfloat16 *w1h = wth + base + 4*DM*DM, *w1l = wtl + base + 4*DM*DM;
        const __nv_bfloat16 *w2h = wth + base + 4*DM*DM + DM*FFD,
                            *w2l = wtl + base + 4*DM*DM + DM*FFD;

        ln_kernel<<<NTOK, 128>>>(x, h, ln1_g + l * DM, ln1_b + l * DM);
        gemm_mma<0><<<gD, 256>>>(h, wqh, wql, bq + l * DM, nullptr, q, DM, DM);
        gemm_mma<0><<<gD, 256>>>(h, wkh, wkl, bk + l * DM, nullptr, k, DM, DM);
        gemm_mma<0><<<gD, 256>>>(h, wvh, wvl, bv + l * DM, nullptr, v, DM, DM);
        attn_kernel<<<dim3(BSZ * HN, TSEQ / 128), 128>>>(q, k, v, att);
        gemm_mma<1><<<gD, 256>>>(att, woh, wol, bo + l * DM, x, x, DM, DM);

        ln_kernel<<<NTOK, 128>>>(x, h, ln2_g + l * DM, ln2_b + l * DM);
        gemm_mma<2><<<gF, 256>>>(h, w1h, w1l, b1 + l * FFD, nullptr, ff, DM, FFD);
        gemm_mma<1><<<gD, 256>>>(ff, w2h, w2l, b2 + l * DM, x, x, FFD, DM);
    }

    // heavy: tanh(((x @ heavy_w) @ heavy_a1) @ heavy_a2 + heavy_b)
    gemm_mma<0><<<gD, 256>>>(x, wth + hb,           wtl + hb,           nullptr, nullptr, h, DM, DM);
    gemm_mma<0><<<gD, 256>>>(h, wth + hb + DM*DM,   wtl + hb + DM*DM,   nullptr, nullptr, q, DM, DM);
    gemm_mma<3><<<gD, 256>>>(q, wth + hb + 2*DM*DM, wtl + hb + 2*DM*DM, heavy_b, nullptr, h, DM, DM);

    ln_kernel<<<NTOK, 128>>>(h, x, norm_g, norm_b);
    pool_kernel<<<dim3(BSZ, DM / 128), 128>>>(x, pool);
    cls_kernel<<<BSZ * NCLS, 128>>>(pool, cls_W, cls_b, out);
    (void)in_sizes; (void)n_in; (void)out_size;
}